// round 13
// baseline (speedup 1.0000x reference)
#include <cuda_runtime.h>
#include <cuda_fp16.h>
#include <cstddef>
#include <cstdint>

// S=32, T=64, B=64, E=H=G=128, C=5
#define M1 131072
#define M2 2048

__device__ float g_xg  [100663296];  // [M1][768]
__device__ float g_out1[33554432];   // [M1][256]
__device__ float g_logit[131072];
__device__ float g_sent[524288];     // [M2][256]
__device__ float g_xg2 [1572864];    // [M2][768]
__device__ float g_out2[524288];     // [M2][256]
__device__ float g_a2  [2048];
__device__ float g_wt  [131072];     // transposed W_W (intra 64K, inter 64K)

__device__ __forceinline__ float sigf(float x) { return 1.f / (1.f + __expf(-x)); }
__device__ __forceinline__ float tanh_clamped(float x) {
    float a = fminf(fmaxf(x, -15.f), 15.f);
    float e = __expf(-2.f * a);
    return (1.f - e) / (1.f + e);
}
__device__ __forceinline__ void mma_f16(float* d, const uint32_t* a, uint32_t b0, uint32_t b1) {
    asm volatile(
        "mma.sync.aligned.m16n8k16.row.col.f32.f16.f16.f32 "
        "{%0,%1,%2,%3}, {%4,%5,%6,%7}, {%8,%9}, {%0,%1,%2,%3};\n"
        : "+f"(d[0]), "+f"(d[1]), "+f"(d[2]), "+f"(d[3])
        : "r"(a[0]), "r"(a[1]), "r"(a[2]), "r"(a[3]), "r"(b0), "r"(b1));
}
__device__ __forceinline__ void ldsm4(uint32_t* r, uint32_t addr) {
    asm volatile("ldmatrix.sync.aligned.m8n8.x4.shared.b16 {%0,%1,%2,%3}, [%4];"
        : "=r"(r[0]), "=r"(r[1]), "=r"(r[2]), "=r"(r[3]) : "r"(addr));
}
// split (a,b) into fp16 hi pair + fp16 residual pair (~22 effective bits)
__device__ __forceinline__ void hsplit(float a, float b, uint32_t& hi, uint32_t& lo) {
    __half ah = __float2half_rn(a);
    __half bh = __float2half_rn(b);
    __half al = __float2half_rn(a - __half2float(ah));
    __half bl = __float2half_rn(b - __half2float(bh));
    hi = ((uint32_t)__half_as_ushort(bh) << 16) | (uint32_t)__half_as_ushort(ah);
    lo = ((uint32_t)__half_as_ushort(bl) << 16) | (uint32_t)__half_as_ushort(al);
}
__device__ __forceinline__ uint32_t hpack(float a, float b) {
    return ((uint32_t)__half_as_ushort(__float2half_rn(b)) << 16)
         | (uint32_t)__half_as_ushort(__float2half_rn(a));
}

// tiny transpose: out[n][h] = in[h][n], 256x256
__global__ void transp256(const float* __restrict__ in, float* __restrict__ out) {
    out[(size_t)threadIdx.x * 256 + blockIdx.x] = in[(size_t)blockIdx.x * 256 + threadIdx.x];
}

// =====================================================================
// fp16 2-term GEMM: C = A'.W^T + bias.  128x128, 256 thr, warps 2m x 4n,
// warp tile 64x32.  acc: Ahi*W (indep chain acc2: Alo*W). smem 104448B.
// =====================================================================
template<bool GATHER>
__global__ void __launch_bounds__(256, 2) gemm_bf(
    const float* __restrict__ A, const int* __restrict__ tokens,
    const float* __restrict__ W, const float* __restrict__ bias,
    float* __restrict__ C, int Ntot, int K)
{
    extern __shared__ uint32_t smg[];
    uint32_t* Ahi = smg;                  // [128][68]
    uint32_t* Alo = smg + 128 * 68;
    uint32_t* Whi = smg + 2 * 128 * 68;
    const int tid = threadIdx.x, lane = tid & 31, w = tid >> 5;
    const int g = lane >> 2, tg = lane & 3;
    const int m0 = blockIdx.y * 128, n0 = blockIdx.x * 128;
    const int mwo = (w >> 2) * 64, nwo = (w & 3) * 32;

    const int lr = tid >> 1;
    size_t arow;
    if (GATHER) arow = (size_t)tokens[m0 + lr] * K;
    else        arow = (size_t)(m0 + lr) * K;
    const size_t wrow = (size_t)(n0 + lr) * K;

    float acc[4][4][4], acc2[4][4][4];
#pragma unroll
    for (int a = 0; a < 4; a++)
#pragma unroll
        for (int b = 0; b < 4; b++)
#pragma unroll
            for (int c = 0; c < 4; c++) { acc[a][b][c] = 0.f; acc2[a][b][c] = 0.f; }

    for (int kc = 0; kc < K; kc += 128) {
#pragma unroll
        for (int i = 0; i < 16; i++) {
            int col = i * 8 + (tid & 1) * 4;
            float4 av = *(const float4*)(A + arow + kc + col);
            float4 wv = *(const float4*)(W + wrow + kc + col);
            int wd = col >> 1;
            uint32_t hi, lo;
            hsplit(av.x, av.y, hi, lo);
            Ahi[lr * 68 + wd] = hi; Alo[lr * 68 + wd] = lo;
            hsplit(av.z, av.w, hi, lo);
            Ahi[lr * 68 + wd + 1] = hi; Alo[lr * 68 + wd + 1] = lo;
            Whi[lr * 68 + wd]     = hpack(wv.x, wv.y);
            Whi[lr * 68 + wd + 1] = hpack(wv.z, wv.w);
        }
        __syncthreads();
#pragma unroll
        for (int kk = 0; kk < 8; kk++) {
            uint32_t ah[4][4], al[4][4];
#pragma unroll
            for (int mt = 0; mt < 4; mt++) {
                const uint32_t* p = Ahi + (mwo + mt * 16 + g) * 68 + kk * 8 + tg;
                ah[mt][0] = p[0]; ah[mt][1] = p[8 * 68];
                ah[mt][2] = p[4]; ah[mt][3] = p[8 * 68 + 4];
                const uint32_t* q = Alo + (mwo + mt * 16 + g) * 68 + kk * 8 + tg;
                al[mt][0] = q[0]; al[mt][1] = q[8 * 68];
                al[mt][2] = q[4]; al[mt][3] = q[8 * 68 + 4];
            }
#pragma unroll
            for (int nt = 0; nt < 4; nt++) {
                const uint32_t* qh = Whi + (nwo + nt * 8 + g) * 68 + kk * 8 + tg;
                uint32_t b0 = qh[0], b1 = qh[4];
#pragma unroll
                for (int mt = 0; mt < 4; mt++) {
                    mma_f16(acc[mt][nt],  ah[mt], b0, b1);   // hi*W
                    mma_f16(acc2[mt][nt], al[mt], b0, b1);   // lo*W (indep chain)
                }
            }
        }
        __syncthreads();
    }
#pragma unroll
    for (int mt = 0; mt < 4; mt++) {
        int r0 = m0 + mwo + mt * 16 + g;
#pragma unroll
        for (int nt = 0; nt < 4; nt++) {
            int col = n0 + nwo + nt * 8 + tg * 2;
            float2 bv = *(const float2*)(bias + col);
            float2 o0 = make_float2(acc[mt][nt][0] + acc2[mt][nt][0] + bv.x,
                                    acc[mt][nt][1] + acc2[mt][nt][1] + bv.y);
            float2 o1 = make_float2(acc[mt][nt][2] + acc2[mt][nt][2] + bv.x,
                                    acc[mt][nt][3] + acc2[mt][nt][3] + bv.y);
            *(float2*)(C + (size_t)r0 * Ntot + col) = o0;
            *(float2*)(C + (size_t)(r0 + 8) * Ntot + col) = o1;
        }
    }
}

// =====================================================================
// fp16 2-term attention: logit[m]=sum_n tanh(A.Wt[n]+bias)*proj.
// BM=128, N=256 full, K-chunks 64. smem 73728B.
// =====================================================================
__global__ void __launch_bounds__(256) att_bf(
    const float* __restrict__ A, const float* __restrict__ Wt,
    const float* __restrict__ bias, const float* __restrict__ proj,
    float* __restrict__ logit)
{
    extern __shared__ uint32_t sma[];
    uint32_t* Ahi = sma;                  // [128][36]
    uint32_t* Alo = sma + 128 * 36;
    uint32_t* Whi = sma + 2 * 128 * 36;   // [256][36]
    const int tid = threadIdx.x, lane = tid & 31, w = tid >> 5;
    const int g = lane >> 2, tg = lane & 3;
    const int m0 = blockIdx.x * 128;
    const int mwo = (w >> 2) * 64, nwo = (w & 3) * 64;

    const int alr = tid >> 1;

    float acc[4][8][4];
#pragma unroll
    for (int a = 0; a < 4; a++)
#pragma unroll
        for (int b = 0; b < 8; b++)
#pragma unroll
            for (int c = 0; c < 4; c++) acc[a][b][c] = 0.f;

    for (int kc = 0; kc < 256; kc += 64) {
#pragma unroll
        for (int i = 0; i < 8; i++) {
            int col = i * 8 + (tid & 1) * 4;
            float4 av = *(const float4*)(A + (size_t)(m0 + alr) * 256 + kc + col);
            int wd = col >> 1;
            uint32_t hi, lo;
            hsplit(av.x, av.y, hi, lo);
            Ahi[alr * 36 + wd] = hi; Alo[alr * 36 + wd] = lo;
            hsplit(av.z, av.w, hi, lo);
            Ahi[alr * 36 + wd + 1] = hi; Alo[alr * 36 + wd + 1] = lo;
        }
#pragma unroll
        for (int i = 0; i < 16; i++) {
            int col = i * 4;
            float4 wv = *(const float4*)(Wt + (size_t)tid * 256 + kc + col);
            int wd = col >> 1;
            Whi[tid * 36 + wd]     = hpack(wv.x, wv.y);
            Whi[tid * 36 + wd + 1] = hpack(wv.z, wv.w);
        }
        __syncthreads();
#pragma unroll
        for (int kk = 0; kk < 4; kk++) {
            uint32_t ah[4][4], al[4][4];
#pragma unroll
            for (int mt = 0; mt < 4; mt++) {
                const uint32_t* p = Ahi + (mwo + mt * 16 + g) * 36 + kk * 8 + tg;
                ah[mt][0] = p[0]; ah[mt][1] = p[8 * 36];
                ah[mt][2] = p[4]; ah[mt][3] = p[8 * 36 + 4];
                const uint32_t* q = Alo + (mwo + mt * 16 + g) * 36 + kk * 8 + tg;
                al[mt][0] = q[0]; al[mt][1] = q[8 * 36];
                al[mt][2] = q[4]; al[mt][3] = q[8 * 36 + 4];
            }
#pragma unroll
            for (int nt = 0; nt < 8; nt++) {
                const uint32_t* qh = Whi + (nwo + nt * 8 + g) * 36 + kk * 8 + tg;
                uint32_t b0 = qh[0], b1 = qh[4];
#pragma unroll
                for (int mt = 0; mt < 4; mt++) {
                    mma_f16(acc[mt][nt], ah[mt], b0, b1);
                    mma_f16(acc[mt][nt], al[mt], b0, b1);
                }
            }
        }
        __syncthreads();
    }
    float* red = (float*)sma;
#pragma unroll
    for (int mt = 0; mt < 4; mt++) {
        float pa = 0.f, pb = 0.f;
#pragma unroll
        for (int nt = 0; nt < 8; nt++) {
            int col = nwo + nt * 8 + tg * 2;
            float2 bv = *(const float2*)(bias + col);
            float2 pv = *(const float2*)(proj + col);
            pa += tanh_clamped(acc[mt][nt][0] + bv.x) * pv.x
                + tanh_clamped(acc[mt][nt][1] + bv.y) * pv.y;
            pb += tanh_clamped(acc[mt][nt][2] + bv.x) * pv.x
                + tanh_clamped(acc[mt][nt][3] + bv.y) * pv.y;
        }
        pa += __shfl_xor_sync(0xffffffffu, pa, 1);
        pa += __shfl_xor_sync(0xffffffffu, pa, 2);
        pb += __shfl_xor_sync(0xffffffffu, pb, 1);
        pb += __shfl_xor_sync(0xffffffffu, pb, 2);
        if (tg == 0) {
            red[(mwo + mt * 16 + g) * 4 + (w & 3)] = pa;
            red[(mwo + mt * 16 + g + 8) * 4 + (w & 3)] = pb;
        }
    }
    __syncthreads();
    if (tid < 128) {
        float s = red[tid * 4] + red[tid * 4 + 1] + red[tid * 4 + 2] + red[tid * 4 + 3];
        logit[m0 + tid] = s;
    }
}

// =====================================================================
// TC GRU recurrence, 16 warps, fp16 2-term, templated MT.
// Bsh [16w][8ks][3t][32] x uint2 (98304B) + h hi/lo [16MT][68].
// =====================================================================
template<int MT>
__global__ void __launch_bounds__(512) gru_rec_tc(
    const float* __restrict__ xg, float* __restrict__ out,
    const float* __restrict__ Whh, const float* __restrict__ bhh,
    int nsteps, size_t chain_xg, size_t chain_out)
{
    extern __shared__ uint32_t smr[];
    uint32_t* Bsh = smr;                 // 24576 u32 (uint2 per lane-entry)
    uint32_t* hhi = smr + 24576;         // [16*MT][68]
    uint32_t* hlo = hhi + 16 * MT * 68;  // [16*MT][68]

    const int tid = threadIdx.x, lane = tid & 31, wrp = tid >> 5;  // 0..15
    const int g = lane >> 2, tg = lane & 3;
    const int dir = blockIdx.y, chain = blockIdx.z;
    const int bCTA = blockIdx.x * 16 * MT;

    const float* wsrc = Whh + (size_t)dir * 384 * 128;
#pragma unroll 2
    for (int ks = 0; ks < 8; ks++)
#pragma unroll
        for (int tt = 0; tt < 3; tt++) {
            int n = tt * 128 + wrp * 8 + g;
            int k = ks * 16 + tg * 2;
            const float* p = wsrc + (size_t)n * 128 + k;
            uint2* dst = (uint2*)Bsh + ((wrp * 8 + ks) * 3 + tt) * 32 + lane;
            *dst = make_uint2(hpack(p[0], p[1]), hpack(p[8], p[9]));
        }
    for (int idx = tid; idx < 16 * MT * 68; idx += 512) { hhi[idx] = 0u; hlo[idx] = 0u; }

    float bn[3][2];
#pragma unroll
    for (int tt = 0; tt < 3; tt++) {
        int n0 = tt * 128 + wrp * 8 + tg * 2;
        float2 v = *(const float2*)(bhh + dir * 384 + n0);
        bn[tt][0] = v.x; bn[tt][1] = v.y;
    }
    float hreg[MT][4];
#pragma unroll
    for (int a = 0; a < MT; a++)
#pragma unroll
        for (int c = 0; c < 4; c++) hreg[a][c] = 0.f;

    uint32_t hhi_sa = (uint32_t)__cvta_generic_to_shared(hhi);
    uint32_t hlo_sa = (uint32_t)__cvta_generic_to_shared(hlo);
    const uint32_t lmoff = (uint32_t)(((lane & 15) * 68 + (lane >> 4) * 4) * 4);

    const float* xbase = xg + chain * chain_xg + dir * 384;
    float* obase = out + chain * chain_out + dir * 128;
    __syncthreads();

    for (int stp = 0; stp < nsteps; stp++) {
        const int t = dir ? (nsteps - 1 - stp) : stp;
        float2 xvv[MT][3][2];
        const float* xrow = xbase + ((size_t)t * 64 + bCTA) * 768;
#pragma unroll
        for (int mt = 0; mt < MT; mt++)
#pragma unroll
            for (int tt = 0; tt < 3; tt++) {
                int n0 = tt * 128 + wrp * 8 + tg * 2;
                xvv[mt][tt][0] = *(const float2*)(xrow + (size_t)(mt * 16 + g) * 768 + n0);
                xvv[mt][tt][1] = *(const float2*)(xrow + (size_t)(mt * 16 + g + 8) * 768 + n0);
            }

        float acc[MT][3][4], acc2[MT][3][4];
#pragma unroll
        for (int mt = 0; mt < MT; mt++)
#pragma unroll
            for (int tt = 0; tt < 3; tt++) {
                acc[mt][tt][0] = bn[tt][0]; acc[mt][tt][1] = bn[tt][1];
                acc[mt][tt][2] = bn[tt][0]; acc[mt][tt][3] = bn[tt][1];
                acc2[mt][tt][0] = 0.f; acc2[mt][tt][1] = 0.f;
                acc2[mt][tt][2] = 0.f; acc2[mt][tt][3] = 0.f;
            }

#pragma unroll
        for (int ks = 0; ks < 8; ks++) {
            uint32_t ahi[MT][4], alo[MT][4];
#pragma unroll
            for (int mt = 0; mt < MT; mt++) {
                uint32_t off = lmoff + (uint32_t)(mt * 16 * 68 * 4 + ks * 32);
                ldsm4(ahi[mt], hhi_sa + off);
                ldsm4(alo[mt], hlo_sa + off);
            }
#pragma unroll
            for (int tt = 0; tt < 3; tt++) {
                uint2 bb = *((const uint2*)Bsh + ((wrp * 8 + ks) * 3 + tt) * 32 + lane);
#pragma unroll
                for (int mt = 0; mt < MT; mt++) {
                    mma_f16(acc[mt][tt],  ahi[mt], bb.x, bb.y);   // hi*W
                    mma_f16(acc2[mt][tt], alo[mt], bb.x, bb.y);   // lo*W (indep chain)
                }
            }
        }
        float hnew[MT][4];
#pragma unroll
        for (int mt = 0; mt < MT; mt++) {
            const float* xr = (const float*)xvv[mt][0];
            const float* xz = (const float*)xvv[mt][1];
            const float* xn = (const float*)xvv[mt][2];
#pragma unroll
            for (int c = 0; c < 4; c++) {
                float rr = sigf(xr[c] + acc[mt][0][c] + acc2[mt][0][c]);
                float zz = sigf(xz[c] + acc[mt][1][c] + acc2[mt][1][c]);
                float nn = tanh_clamped(xn[c] + rr * (acc[mt][2][c] + acc2[mt][2][c]));
                float h  = (1.f - zz) * nn + zz * hreg[mt][c];
                hreg[mt][c] = h;
                hnew[mt][c] = h;
            }
        }
        __syncthreads();   // all ldmatrix reads of old h done
        const int wcol = wrp * 4 + tg;
#pragma unroll
        for (int mt = 0; mt < MT; mt++) {
            int r0 = mt * 16 + g, r1 = r0 + 8;
            uint32_t hi, lo;
            hsplit(hnew[mt][0], hnew[mt][1], hi, lo);
            hhi[r0 * 68 + wcol] = hi; hlo[r0 * 68 + wcol] = lo;
            hsplit(hnew[mt][2], hnew[mt][3], hi, lo);
            hhi[r1 * 68 + wcol] = hi; hlo[r1 * 68 + wcol] = lo;
            int j0 = wrp * 8 + tg * 2;
            *(float2*)(obase + ((size_t)t * 64 + bCTA + r0) * 256 + j0) =
                make_float2(hnew[mt][0], hnew[mt][1]);
            *(float2*)(obase + ((size_t)t * 64 + bCTA + r1) * 256 + j0) =
                make_float2(hnew[mt][2], hnew[mt][3]);
        }
        __syncthreads();   // new h visible before next step's ldmatrix
    }
}

// ===================== softmax over T + weighted sum =================
__global__ void __launch_bounds__(256) softk(
    const float* __restrict__ logit, const float* __restrict__ out1,
    float* __restrict__ sent)
{
    const int s = blockIdx.x, b = blockIdx.y, tid = threadIdx.x;
    __shared__ float w[64];
    if (tid < 64) w[tid] = logit[(s * 64 + tid) * 64 + b];
    __syncthreads();
    if (tid < 32) {
        float a0 = w[tid], a1 = w[tid + 32];
        float mx = fmaxf(a0, a1);
#pragma unroll
        for (int off = 16; off > 0; off >>= 1)
            mx = fmaxf(mx, __shfl_xor_sync(0xffffffffu, mx, off));
        float e0 = __expf(a0 - mx), e1 = __expf(a1 - mx);
        float sum = e0 + e1;
#pragma unroll
        for (int off = 16; off > 0; off >>= 1)
            sum += __shfl_xor_sync(0xffffffffu, sum, off);
        float inv = 1.f / sum;
        w[tid] = e0 * inv; w[tid + 32] = e1 * inv;
    }
    __syncthreads();
    float acc = 0.f;
    const float* base = out1 + ((size_t)s * 64 * 64 + b) * 256 + tid;
#pragma unroll 8
    for (int t = 0; t < 64; t++)
        acc += w[t] * base[(size_t)t * 64 * 256];
    sent[(size_t)(s * 64 + b) * 256 + tid] = acc;
}

// ===================== final: doc vec + linear =======================
__global__ void __launch_bounds__(256) finalk(
    const float* __restrict__ out2, const float* __restrict__ a2,
    const float* __restrict__ Wf, const float* __restrict__ bf,
    float* __restrict__ out)
{
    const int b = blockIdx.x, tid = threadIdx.x;
    __shared__ float doc[256];
    float acc = 0.f;
#pragma unroll 8
    for (int s = 0; s < 32; s++)
        acc += a2[s * 64 + b] * out2[(size_t)(s * 64 + b) * 256 + tid];
    doc[tid] = acc;
    __syncthreads();
    if (tid < 5) {
        float r = bf[tid];
        for (int h = 0; h < 256; h++) r += doc[h] * Wf[tid * 256 + h];
        out[b * 5 + tid] = r;
    }
}

// =====================================================================
extern "C" void kernel_launch(void* const* d_in, const int* in_sizes, int n_in,
                              void* d_out, int out_size)
{
    (void)in_sizes; (void)n_in; (void)out_size;
    const int*   tokens = (const int*)  d_in[0];
    const float* embed  = (const float*)d_in[1];
    const float* Wih_a  = (const float*)d_in[2];
    const float* Whh_a  = (const float*)d_in[3];
    const float* bih_a  = (const float*)d_in[4];
    const float* bhh_a  = (const float*)d_in[5];
    const float* WW_a   = (const float*)d_in[6];
    const float* b_a    = (const float*)d_in[7];
    const float* proj_a = (const float*)d_in[8];
    const float* Wih_b  = (const float*)d_in[9];
    const float* Whh_b  = (const float*)d_in[10];
    const float* bih_b  = (const float*)d_in[11];
    const float* bhh_b  = (const float*)d_in[12];
    const float* WW_b   = (const float*)d_in[13];
    const float* b_b    = (const float*)d_in[14];
    const float* proj_b = (const float*)d_in[15];
    const float* Wf     = (const float*)d_in[16];
    const float* bf     = (const float*)d_in[17];
    float* out = (float*)d_out;

    float *xg, *out1, *logit, *sent, *xg2, *out2, *a2, *wt;
    cudaGetSymbolAddress((void**)&xg,    g_xg);
    cudaGetSymbolAddress((void**)&out1,  g_out1);
    cudaGetSymbolAddress((void**)&logit, g_logit);
    cudaGetSymbolAddress((void**)&sent,  g_sent);
    cudaGetSymbolAddress((void**)&xg2,   g_xg2);
    cudaGetSymbolAddress((void**)&out2,  g_out2);
    cudaGetSymbolAddress((void**)&a2,    g_a2);
    cudaGetSymbolAddress((void**)&wt,    g_wt);

    const int gru2_smem = (24576 + 2 * 32 * 68) * (int)sizeof(uint32_t);      // 115712
    const int gru1_smem = (24576 + 2 * 16 * 68) * (int)sizeof(uint32_t);      // 107008
    const int gemm_smem = 3 * 128 * 68 * (int)sizeof(uint32_t);               // 104448
    const int att_smem  = (2 * 128 * 36 + 256 * 36) * (int)sizeof(uint32_t);  // 73728
    cudaFuncSetAttribute(gru_rec_tc<2>, cudaFuncAttributeMaxDynamicSharedMemorySize, gru2_smem);
    cudaFuncSetAttribute(gru_rec_tc<1>, cudaFuncAttributeMaxDynamicSharedMemorySize, gru1_smem);
    cudaFuncSetAttribute(gemm_bf<true>, cudaFuncAttributeMaxDynamicSharedMemorySize, gemm_smem);
    cudaFuncSetAttribute(gemm_bf<false>,cudaFuncAttributeMaxDynamicSharedMemorySize, gemm_smem);
    cudaFuncSetAttribute(att_bf,        cudaFuncAttributeMaxDynamicSharedMemorySize, att_smem);

    // 0) one-time transposes of the two attention weight matrices
    transp256<<<256, 256>>>(WW_a, wt);
    transp256<<<256, 256>>>(WW_b, wt + 65536);
    // 1) intra input gates: gather(emb) @ Wih_intra^T + bih
    gemm_bf<true><<<dim3(6, 1024), 256, gemm_smem>>>(embed, tokens, Wih_a, bih_a, xg, 768, 128);
    // 2) intra biGRU (MT=2: 32-batch tiles, 128 CTAs)
    gru_rec_tc<2><<<dim3(2, 2, 32), 512, gru2_smem>>>(
        xg, out1, Whh_a, bhh_a, 64, (size_t)64 * 64 * 768, (size_t)64 * 64 * 256);
    // 3) token attention logits
    att_bf<<<1024, 256, att_smem>>>(out1, wt, b_a, proj_a, logit);
    // 4) softmax over tokens + weighted sum
    softk<<<dim3(32, 64), 256>>>(logit, out1, sent);
    // 5) inter input gates
    gemm_bf<false><<<dim3(6, 16), 256, gemm_smem>>>(sent, nullptr, Wih_b, bih_b, xg2, 768, 256);
    // 6) inter biGRU (MT=1: 16-batch tiles, 8 CTAs)
    gru_rec_tc<1><<<dim3(4, 2, 1), 512, gru1_smem>>>(xg2, out2, Whh_b, bhh_b, 32, 0, 0);
    // 7) sentence attention scores (no softmax)
    att_bf<<<16, 256, att_smem>>>(out2, wt + 65536, b_b, proj_b, a2);
    // 8) doc vector + final linear
    finalk<<<64, 256>>>(out2, a2, Wf, bf, out);
}

// round 15
// speedup vs baseline: 1.3050x; 1.3050x over previous
#include <cuda_runtime.h>
#include <cuda_fp16.h>
#include <cstddef>
#include <cstdint>

// S=32, T=64, B=64, E=H=G=128, C=5
#define M1 131072
#define M2 2048

__device__ float g_xg  [100663296];  // [M1][768]
__device__ float g_out1[33554432];   // [M1][256]
__device__ float g_logit[131072];
__device__ float g_sent[524288];     // [M2][256]
__device__ float g_xg2 [1572864];    // [M2][768]
__device__ float g_out2[524288];     // [M2][256]
__device__ float g_a2  [2048];
__device__ float g_wt  [131072];     // transposed W_W (intra 64K, inter 64K)

__device__ __forceinline__ float sigf(float x) { return 1.f / (1.f + __expf(-x)); }
__device__ __forceinline__ float tanh_clamped(float x) {
    float a = fminf(fmaxf(x, -15.f), 15.f);
    float e = __expf(-2.f * a);
    return (1.f - e) / (1.f + e);
}
__device__ __forceinline__ void mma_f16(float* d, const uint32_t* a, uint32_t b0, uint32_t b1) {
    asm volatile(
        "mma.sync.aligned.m16n8k16.row.col.f32.f16.f16.f32 "
        "{%0,%1,%2,%3}, {%4,%5,%6,%7}, {%8,%9}, {%0,%1,%2,%3};\n"
        : "+f"(d[0]), "+f"(d[1]), "+f"(d[2]), "+f"(d[3])
        : "r"(a[0]), "r"(a[1]), "r"(a[2]), "r"(a[3]), "r"(b0), "r"(b1));
}
__device__ __forceinline__ void ldsm4(uint32_t* r, uint32_t addr) {
    asm volatile("ldmatrix.sync.aligned.m8n8.x4.shared.b16 {%0,%1,%2,%3}, [%4];"
        : "=r"(r[0]), "=r"(r[1]), "=r"(r[2]), "=r"(r[3]) : "r"(addr));
}
// split (a,b) into fp16 hi pair + fp16 residual pair (~22 effective bits)
__device__ __forceinline__ void hsplit(float a, float b, uint32_t& hi, uint32_t& lo) {
    __half ah = __float2half_rn(a);
    __half bh = __float2half_rn(b);
    __half al = __float2half_rn(a - __half2float(ah));
    __half bl = __float2half_rn(b - __half2float(bh));
    hi = ((uint32_t)__half_as_ushort(bh) << 16) | (uint32_t)__half_as_ushort(ah);
    lo = ((uint32_t)__half_as_ushort(bl) << 16) | (uint32_t)__half_as_ushort(al);
}
__device__ __forceinline__ uint32_t hpack(float a, float b) {
    return ((uint32_t)__half_as_ushort(__float2half_rn(b)) << 16)
         | (uint32_t)__half_as_ushort(__float2half_rn(a));
}

// tiny transpose: out[n][h] = in[h][n], 256x256
__global__ void transp256(const float* __restrict__ in, float* __restrict__ out) {
    out[(size_t)threadIdx.x * 256 + blockIdx.x] = in[(size_t)blockIdx.x * 256 + threadIdx.x];
}

// =====================================================================
// fp16 2-term GEMM: C = A'.W^T + bias.  128x128, 256 thr, warps 2m x 4n,
// warp tile 64x32.  acc: Ahi*W, acc2: Alo*W (indep chains).
// NO min-blocks clamp: acc+acc2 need ~190 regs, spill-free at 1 CTA/SM.
// =====================================================================
template<bool GATHER>
__global__ void __launch_bounds__(256) gemm_bf(
    const float* __restrict__ A, const int* __restrict__ tokens,
    const float* __restrict__ W, const float* __restrict__ bias,
    float* __restrict__ C, int Ntot, int K)
{
    extern __shared__ uint32_t smg[];
    uint32_t* Ahi = smg;                  // [128][68]
    uint32_t* Alo = smg + 128 * 68;
    uint32_t* Whi = smg + 2 * 128 * 68;
    const int tid = threadIdx.x, lane = tid & 31, w = tid >> 5;
    const int g = lane >> 2, tg = lane & 3;
    const int m0 = blockIdx.y * 128, n0 = blockIdx.x * 128;
    const int mwo = (w >> 2) * 64, nwo = (w & 3) * 32;

    const int lr = tid >> 1;
    size_t arow;
    if (GATHER) arow = (size_t)tokens[m0 + lr] * K;
    else        arow = (size_t)(m0 + lr) * K;
    const size_t wrow = (size_t)(n0 + lr) * K;

    float acc[4][4][4], acc2[4][4][4];
#pragma unroll
    for (int a = 0; a < 4; a++)
#pragma unroll
        for (int b = 0; b < 4; b++)
#pragma unroll
            for (int c = 0; c < 4; c++) { acc[a][b][c] = 0.f; acc2[a][b][c] = 0.f; }

    for (int kc = 0; kc < K; kc += 128) {
#pragma unroll
        for (int i = 0; i < 16; i++) {
            int col = i * 8 + (tid & 1) * 4;
            float4 av = *(const float4*)(A + arow + kc + col);
            float4 wv = *(const float4*)(W + wrow + kc + col);
            int wd = col >> 1;
            uint32_t hi, lo;
            hsplit(av.x, av.y, hi, lo);
            Ahi[lr * 68 + wd] = hi; Alo[lr * 68 + wd] = lo;
            hsplit(av.z, av.w, hi, lo);
            Ahi[lr * 68 + wd + 1] = hi; Alo[lr * 68 + wd + 1] = lo;
            Whi[lr * 68 + wd]     = hpack(wv.x, wv.y);
            Whi[lr * 68 + wd + 1] = hpack(wv.z, wv.w);
        }
        __syncthreads();
#pragma unroll
        for (int kk = 0; kk < 8; kk++) {
            uint32_t ah[4][4], al[4][4];
#pragma unroll
            for (int mt = 0; mt < 4; mt++) {
                const uint32_t* p = Ahi + (mwo + mt * 16 + g) * 68 + kk * 8 + tg;
                ah[mt][0] = p[0]; ah[mt][1] = p[8 * 68];
                ah[mt][2] = p[4]; ah[mt][3] = p[8 * 68 + 4];
                const uint32_t* q = Alo + (mwo + mt * 16 + g) * 68 + kk * 8 + tg;
                al[mt][0] = q[0]; al[mt][1] = q[8 * 68];
                al[mt][2] = q[4]; al[mt][3] = q[8 * 68 + 4];
            }
#pragma unroll
            for (int nt = 0; nt < 4; nt++) {
                const uint32_t* qh = Whi + (nwo + nt * 8 + g) * 68 + kk * 8 + tg;
                uint32_t b0 = qh[0], b1 = qh[4];
#pragma unroll
                for (int mt = 0; mt < 4; mt++) {
                    mma_f16(acc[mt][nt],  ah[mt], b0, b1);   // hi*W
                    mma_f16(acc2[mt][nt], al[mt], b0, b1);   // lo*W (indep chain)
                }
            }
        }
        __syncthreads();
    }
#pragma unroll
    for (int mt = 0; mt < 4; mt++) {
        int r0 = m0 + mwo + mt * 16 + g;
#pragma unroll
        for (int nt = 0; nt < 4; nt++) {
            int col = n0 + nwo + nt * 8 + tg * 2;
            float2 bv = *(const float2*)(bias + col);
            float2 o0 = make_float2(acc[mt][nt][0] + acc2[mt][nt][0] + bv.x,
                                    acc[mt][nt][1] + acc2[mt][nt][1] + bv.y);
            float2 o1 = make_float2(acc[mt][nt][2] + acc2[mt][nt][2] + bv.x,
                                    acc[mt][nt][3] + acc2[mt][nt][3] + bv.y);
            *(float2*)(C + (size_t)r0 * Ntot + col) = o0;
            *(float2*)(C + (size_t)(r0 + 8) * Ntot + col) = o1;
        }
    }
}

// =====================================================================
// fp16 2-term attention: logit[m]=sum_n tanh(A.Wt[n]+bias)*proj.
// BM=128, N=256 full, K-chunks 64. smem 73728B.
// =====================================================================
__global__ void __launch_bounds__(256) att_bf(
    const float* __restrict__ A, const float* __restrict__ Wt,
    const float* __restrict__ bias, const float* __restrict__ proj,
    float* __restrict__ logit)
{
    extern __shared__ uint32_t sma[];
    uint32_t* Ahi = sma;                  // [128][36]
    uint32_t* Alo = sma + 128 * 36;
    uint32_t* Whi = sma + 2 * 128 * 36;   // [256][36]
    const int tid = threadIdx.x, lane = tid & 31, w = tid >> 5;
    const int g = lane >> 2, tg = lane & 3;
    const int m0 = blockIdx.x * 128;
    const int mwo = (w >> 2) * 64, nwo = (w & 3) * 64;

    const int alr = tid >> 1;

    float acc[4][8][4];
#pragma unroll
    for (int a = 0; a < 4; a++)
#pragma unroll
        for (int b = 0; b < 8; b++)
#pragma unroll
            for (int c = 0; c < 4; c++) acc[a][b][c] = 0.f;

    for (int kc = 0; kc < 256; kc += 64) {
#pragma unroll
        for (int i = 0; i < 8; i++) {
            int col = i * 8 + (tid & 1) * 4;
            float4 av = *(const float4*)(A + (size_t)(m0 + alr) * 256 + kc + col);
            int wd = col >> 1;
            uint32_t hi, lo;
            hsplit(av.x, av.y, hi, lo);
            Ahi[alr * 36 + wd] = hi; Alo[alr * 36 + wd] = lo;
            hsplit(av.z, av.w, hi, lo);
            Ahi[alr * 36 + wd + 1] = hi; Alo[alr * 36 + wd + 1] = lo;
        }
#pragma unroll
        for (int i = 0; i < 16; i++) {
            int col = i * 4;
            float4 wv = *(const float4*)(Wt + (size_t)tid * 256 + kc + col);
            int wd = col >> 1;
            Whi[tid * 36 + wd]     = hpack(wv.x, wv.y);
            Whi[tid * 36 + wd + 1] = hpack(wv.z, wv.w);
        }
        __syncthreads();
#pragma unroll
        for (int kk = 0; kk < 4; kk++) {
            uint32_t ah[4][4], al[4][4];
#pragma unroll
            for (int mt = 0; mt < 4; mt++) {
                const uint32_t* p = Ahi + (mwo + mt * 16 + g) * 36 + kk * 8 + tg;
                ah[mt][0] = p[0]; ah[mt][1] = p[8 * 36];
                ah[mt][2] = p[4]; ah[mt][3] = p[8 * 36 + 4];
                const uint32_t* q = Alo + (mwo + mt * 16 + g) * 36 + kk * 8 + tg;
                al[mt][0] = q[0]; al[mt][1] = q[8 * 36];
                al[mt][2] = q[4]; al[mt][3] = q[8 * 36 + 4];
            }
#pragma unroll
            for (int nt = 0; nt < 8; nt++) {
                const uint32_t* qh = Whi + (nwo + nt * 8 + g) * 36 + kk * 8 + tg;
                uint32_t b0 = qh[0], b1 = qh[4];
#pragma unroll
                for (int mt = 0; mt < 4; mt++) {
                    mma_f16(acc[mt][nt], ah[mt], b0, b1);
                    mma_f16(acc[mt][nt], al[mt], b0, b1);
                }
            }
        }
        __syncthreads();
    }
    float* red = (float*)sma;
#pragma unroll
    for (int mt = 0; mt < 4; mt++) {
        float pa = 0.f, pb = 0.f;
#pragma unroll
        for (int nt = 0; nt < 8; nt++) {
            int col = nwo + nt * 8 + tg * 2;
            float2 bv = *(const float2*)(bias + col);
            float2 pv = *(const float2*)(proj + col);
            pa += tanh_clamped(acc[mt][nt][0] + bv.x) * pv.x
                + tanh_clamped(acc[mt][nt][1] + bv.y) * pv.y;
            pb += tanh_clamped(acc[mt][nt][2] + bv.x) * pv.x
                + tanh_clamped(acc[mt][nt][3] + bv.y) * pv.y;
        }
        pa += __shfl_xor_sync(0xffffffffu, pa, 1);
        pa += __shfl_xor_sync(0xffffffffu, pa, 2);
        pb += __shfl_xor_sync(0xffffffffu, pb, 1);
        pb += __shfl_xor_sync(0xffffffffu, pb, 2);
        if (tg == 0) {
            red[(mwo + mt * 16 + g) * 4 + (w & 3)] = pa;
            red[(mwo + mt * 16 + g + 8) * 4 + (w & 3)] = pb;
        }
    }
    __syncthreads();
    if (tid < 128) {
        float s = red[tid * 4] + red[tid * 4 + 1] + red[tid * 4 + 2] + red[tid * 4 + 3];
        logit[m0 + tid] = s;
    }
}

// =====================================================================
// TC GRU recurrence, 16 warps, fp16 2-term, templated MT. (R13, 313us)
// =====================================================================
template<int MT>
__global__ void __launch_bounds__(512) gru_rec_tc(
    const float* __restrict__ xg, float* __restrict__ out,
    const float* __restrict__ Whh, const float* __restrict__ bhh,
    int nsteps, size_t chain_xg, size_t chain_out)
{
    extern __shared__ uint32_t smr[];
    uint32_t* Bsh = smr;                 // 24576 u32 (uint2 per lane-entry)
    uint32_t* hhi = smr + 24576;         // [16*MT][68]
    uint32_t* hlo = hhi + 16 * MT * 68;  // [16*MT][68]

    const int tid = threadIdx.x, lane = tid & 31, wrp = tid >> 5;  // 0..15
    const int g = lane >> 2, tg = lane & 3;
    const int dir = blockIdx.y, chain = blockIdx.z;
    const int bCTA = blockIdx.x * 16 * MT;

    const float* wsrc = Whh + (size_t)dir * 384 * 128;
#pragma unroll 2
    for (int ks = 0; ks < 8; ks++)
#pragma unroll
        for (int tt = 0; tt < 3; tt++) {
            int n = tt * 128 + wrp * 8 + g;
            int k = ks * 16 + tg * 2;
            const float* p = wsrc + (size_t)n * 128 + k;
            uint2* dst = (uint2*)Bsh + ((wrp * 8 + ks) * 3 + tt) * 32 + lane;
            *dst = make_uint2(hpack(p[0], p[1]), hpack(p[8], p[9]));
        }
    for (int idx = tid; idx < 16 * MT * 68; idx += 512) { hhi[idx] = 0u; hlo[idx] = 0u; }

    float bn[3][2];
#pragma unroll
    for (int tt = 0; tt < 3; tt++) {
        int n0 = tt * 128 + wrp * 8 + tg * 2;
        float2 v = *(const float2*)(bhh + dir * 384 + n0);
        bn[tt][0] = v.x; bn[tt][1] = v.y;
    }
    float hreg[MT][4];
#pragma unroll
    for (int a = 0; a < MT; a++)
#pragma unroll
        for (int c = 0; c < 4; c++) hreg[a][c] = 0.f;

    uint32_t hhi_sa = (uint32_t)__cvta_generic_to_shared(hhi);
    uint32_t hlo_sa = (uint32_t)__cvta_generic_to_shared(hlo);
    const uint32_t lmoff = (uint32_t)(((lane & 15) * 68 + (lane >> 4) * 4) * 4);

    const float* xbase = xg + chain * chain_xg + dir * 384;
    float* obase = out + chain * chain_out + dir * 128;
    __syncthreads();

    for (int stp = 0; stp < nsteps; stp++) {
        const int t = dir ? (nsteps - 1 - stp) : stp;
        float2 xvv[MT][3][2];
        const float* xrow = xbase + ((size_t)t * 64 + bCTA) * 768;
#pragma unroll
        for (int mt = 0; mt < MT; mt++)
#pragma unroll
            for (int tt = 0; tt < 3; tt++) {
                int n0 = tt * 128 + wrp * 8 + tg * 2;
                xvv[mt][tt][0] = *(const float2*)(xrow + (size_t)(mt * 16 + g) * 768 + n0);
                xvv[mt][tt][1] = *(const float2*)(xrow + (size_t)(mt * 16 + g + 8) * 768 + n0);
            }

        float acc[MT][3][4], acc2[MT][3][4];
#pragma unroll
        for (int mt = 0; mt < MT; mt++)
#pragma unroll
            for (int tt = 0; tt < 3; tt++) {
                acc[mt][tt][0] = bn[tt][0]; acc[mt][tt][1] = bn[tt][1];
                acc[mt][tt][2] = bn[tt][0]; acc[mt][tt][3] = bn[tt][1];
                acc2[mt][tt][0] = 0.f; acc2[mt][tt][1] = 0.f;
                acc2[mt][tt][2] = 0.f; acc2[mt][tt][3] = 0.f;
            }

#pragma unroll
        for (int ks = 0; ks < 8; ks++) {
            uint32_t ahi[MT][4], alo[MT][4];
#pragma unroll
            for (int mt = 0; mt < MT; mt++) {
                uint32_t off = lmoff + (uint32_t)(mt * 16 * 68 * 4 + ks * 32);
                ldsm4(ahi[mt], hhi_sa + off);
                ldsm4(alo[mt], hlo_sa + off);
            }
#pragma unroll
            for (int tt = 0; tt < 3; tt++) {
                uint2 bb = *((const uint2*)Bsh + ((wrp * 8 + ks) * 3 + tt) * 32 + lane);
#pragma unroll
                for (int mt = 0; mt < MT; mt++) {
                    mma_f16(acc[mt][tt],  ahi[mt], bb.x, bb.y);   // hi*W
                    mma_f16(acc2[mt][tt], alo[mt], bb.x, bb.y);   // lo*W (indep chain)
                }
            }
        }
        float hnew[MT][4];
#pragma unroll
        for (int mt = 0; mt < MT; mt++) {
            const float* xr = (const float*)xvv[mt][0];
            const float* xz = (const float*)xvv[mt][1];
            const float* xn = (const float*)xvv[mt][2];
#pragma unroll
            for (int c = 0; c < 4; c++) {
                float rr = sigf(xr[c] + acc[mt][0][c] + acc2[mt][0][c]);
                float zz = sigf(xz[c] + acc[mt][1][c] + acc2[mt][1][c]);
                float nn = tanh_clamped(xn[c] + rr * (acc[mt][2][c] + acc2[mt][2][c]));
                float h  = (1.f - zz) * nn + zz * hreg[mt][c];
                hreg[mt][c] = h;
                hnew[mt][c] = h;
            }
        }
        __syncthreads();   // all ldmatrix reads of old h done
        const int wcol = wrp * 4 + tg;
#pragma unroll
        for (int mt = 0; mt < MT; mt++) {
            int r0 = mt * 16 + g, r1 = r0 + 8;
            uint32_t hi, lo;
            hsplit(hnew[mt][0], hnew[mt][1], hi, lo);
            hhi[r0 * 68 + wcol] = hi; hlo[r0 * 68 + wcol] = lo;
            hsplit(hnew[mt][2], hnew[mt][3], hi, lo);
            hhi[r1 * 68 + wcol] = hi; hlo[r1 * 68 + wcol] = lo;
            int j0 = wrp * 8 + tg * 2;
            *(float2*)(obase + ((size_t)t * 64 + bCTA + r0) * 256 + j0) =
                make_float2(hnew[mt][0], hnew[mt][1]);
            *(float2*)(obase + ((size_t)t * 64 + bCTA + r1) * 256 + j0) =
                make_float2(hnew[mt][2], hnew[mt][3]);
        }
        __syncthreads();   // new h visible before next step's ldmatrix
    }
}

// ===================== softmax over T + weighted sum =================
__global__ void __launch_bounds__(256) softk(
    const float* __restrict__ logit, const float* __restrict__ out1,
    float* __restrict__ sent)
{
    const int s = blockIdx.x, b = blockIdx.y, tid = threadIdx.x;
    __shared__ float w[64];
    if (tid < 64) w[tid] = logit[(s * 64 + tid) * 64 + b];
    __syncthreads();
    if (tid < 32) {
        float a0 = w[tid], a1 = w[tid + 32];
        float mx = fmaxf(a0, a1);
#pragma unroll
        for (int off = 16; off > 0; off >>= 1)
            mx = fmaxf(mx, __shfl_xor_sync(0xffffffffu, mx, off));
        float e0 = __expf(a0 - mx), e1 = __expf(a1 - mx);
        float sum = e0 + e1;
#pragma unroll
        for (int off = 16; off > 0; off >>= 1)
            sum += __shfl_xor_sync(0xffffffffu, sum, off);
        float inv = 1.f / sum;
        w[tid] = e0 * inv; w[tid + 32] = e1 * inv;
    }
    __syncthreads();
    float acc = 0.f;
    const float* base = out1 + ((size_t)s * 64 * 64 + b) * 256 + tid;
#pragma unroll 8
    for (int t = 0; t < 64; t++)
        acc += w[t] * base[(size_t)t * 64 * 256];
    sent[(size_t)(s * 64 + b) * 256 + tid] = acc;
}

// ===================== final: doc vec + linear =======================
__global__ void __launch_bounds__(256) finalk(
    const float* __restrict__ out2, const float* __restrict__ a2,
    const float* __restrict__ Wf, const float* __restrict__ bf,
    float* __restrict__ out)
{
    const int b = blockIdx.x, tid = threadIdx.x;
    __shared__ float doc[256];
    float acc = 0.f;
#pragma unroll 8
    for (int s = 0; s < 32; s++)
        acc += a2[s * 64 + b] * out2[(size_t)(s * 64 + b) * 256 + tid];
    doc[tid] = acc;
    __syncthreads();
    if (tid < 5) {
        float r = bf[tid];
        for (int h = 0; h < 256; h++) r += doc[h] * Wf[tid * 256 + h];
        out[b * 5 + tid] = r;
    }
}

// =====================================================================
extern "C" void kernel_launch(void* const* d_in, const int* in_sizes, int n_in,
                              void* d_out, int out_size)
{
    (void)in_sizes; (void)n_in; (void)out_size;
    const int*   tokens = (const int*)  d_in[0];
    const float* embed  = (const float*)d_in[1];
    const float* Wih_a  = (const float*)d_in[2];
    const float* Whh_a  = (const float*)d_in[3];
    const float* bih_a  = (const float*)d_in[4];
    const float* bhh_a  = (const float*)d_in[5];
    const float* WW_a   = (const float*)d_in[6];
    const float* b_a    = (const float*)d_in[7];
    const float* proj_a = (const float*)d_in[8];
    const float* Wih_b  = (const float*)d_in[9];
    const float* Whh_b  = (const float*)d_in[10];
    const float* bih_b  = (const float*)d_in[11];
    const float* bhh_b  = (const float*)d_in[12];
    const float* WW_b   = (const float*)d_in[13];
    const float* b_b    = (const float*)d_in[14];
    const float* proj_b = (const float*)d_in[15];
    const float* Wf     = (const float*)d_in[16];
    const float* bf     = (const float*)d_in[17];
    float* out = (float*)d_out;

    float *xg, *out1, *logit, *sent, *xg2, *out2, *a2, *wt;
    cudaGetSymbolAddress((void**)&xg,    g_xg);
    cudaGetSymbolAddress((void**)&out1,  g_out1);
    cudaGetSymbolAddress((void**)&logit, g_logit);
    cudaGetSymbolAddress((void**)&sent,  g_sent);
    cudaGetSymbolAddress((void**)&xg2,   g_xg2);
    cudaGetSymbolAddress((void**)&out2,  g_out2);
    cudaGetSymbolAddress((void**)&a2,    g_a2);
    cudaGetSymbolAddress((void**)&wt,    g_wt);

    const int gru2_smem = (24576 + 2 * 32 * 68) * (int)sizeof(uint32_t);      // 115712
    const int gru1_smem = (24576 + 2 * 16 * 68) * (int)sizeof(uint32_t);      // 107008
    const int gemm_smem = 3 * 128 * 68 * (int)sizeof(uint32_t);               // 104448
    const int att_smem  = (2 * 128 * 36 + 256 * 36) * (int)sizeof(uint32_t);  // 73728
    cudaFuncSetAttribute(gru_rec_tc<2>, cudaFuncAttributeMaxDynamicSharedMemorySize, gru2_smem);
    cudaFuncSetAttribute(gru_rec_tc<1>, cudaFuncAttributeMaxDynamicSharedMemorySize, gru1_smem);
    cudaFuncSetAttribute(gemm_bf<true>, cudaFuncAttributeMaxDynamicSharedMemorySize, gemm_smem);
    cudaFuncSetAttribute(gemm_bf<false>,cudaFuncAttributeMaxDynamicSharedMemorySize, gemm_smem);
    cudaFuncSetAttribute(att_bf,        cudaFuncAttributeMaxDynamicSharedMemorySize, att_smem);

    // 0) one-time transposes of the two attention weight matrices
    transp256<<<256, 256>>>(WW_a, wt);
    transp256<<<256, 256>>>(WW_b, wt + 65536);
    // 1) intra input gates: gather(emb) @ Wih_intra^T + bih
    gemm_bf<true><<<dim3(6, 1024), 256, gemm_smem>>>(embed, tokens, Wih_a, bih_a, xg, 768, 128);
    // 2) intra biGRU (MT=2: 32-batch tiles, 128 CTAs)
    gru_rec_tc<2><<<dim3(2, 2, 32), 512, gru2_smem>>>(
        xg, out1, Whh_a, bhh_a, 64, (size_t)64 * 64 * 768, (size_t)64 * 64 * 256);
    // 3) token attention logits
    att_bf<<<1024, 256, att_smem>>>(out1, wt, b_a, proj_a, logit);
    // 4) softmax over tokens + weighted sum
    softk<<<dim3(32, 64), 256>>>(logit, out1, sent);
    // 5) inter input gates
    gemm_bf<false><<<dim3(6, 16), 256, gemm_smem>>>(sent, nullptr, Wih_b, bih_b, xg2, 768, 256);
    // 6) inter biGRU (MT=1: 16-batch tiles, 8 CTAs)
    gru_rec_tc<1><<<dim3(4, 2, 1), 512, gru1_smem>>>(xg2, out2, Whh_b, bhh_b, 32, 0, 0);
    // 7) sentence attention scores (no softmax)
    att_bf<<<16, 256, att_smem>>>(out2, wt + 65536, b_b, proj_b, a2);
    // 8) doc vector + final linear
    finalk<<<64, 256>>>(out2, a2, Wf, bf, out);
}

// round 16
// speedup vs baseline: 1.5386x; 1.1790x over previous
#include <cuda_runtime.h>
#include <cuda_fp16.h>
#include <cstddef>
#include <cstdint>

// S=32, T=64, B=64, E=H=G=128, C=5
#define M1 131072
#define M2 2048

__device__ float g_xg  [100663296];  // [M1][768]
__device__ float g_out1[33554432];   // [M1][256]
__device__ float g_logit[131072];
__device__ float g_sent[524288];     // [M2][256]
__device__ float g_xg2 [1572864];    // [M2][768]
__device__ float g_out2[524288];     // [M2][256]
__device__ float g_a2  [2048];
__device__ float g_wt  [131072];     // transposed W_W (intra 64K, inter 64K)

__device__ __forceinline__ float sigf(float x) { return 1.f / (1.f + __expf(-x)); }
__device__ __forceinline__ float tanh_clamped(float x) {
    float a = fminf(fmaxf(x, -15.f), 15.f);
    float e = __expf(-2.f * a);
    return (1.f - e) / (1.f + e);
}
__device__ __forceinline__ void mma_f16(float* d, const uint32_t* a, uint32_t b0, uint32_t b1) {
    asm volatile(
        "mma.sync.aligned.m16n8k16.row.col.f32.f16.f16.f32 "
        "{%0,%1,%2,%3}, {%4,%5,%6,%7}, {%8,%9}, {%0,%1,%2,%3};\n"
        : "+f"(d[0]), "+f"(d[1]), "+f"(d[2]), "+f"(d[3])
        : "r"(a[0]), "r"(a[1]), "r"(a[2]), "r"(a[3]), "r"(b0), "r"(b1));
}
__device__ __forceinline__ void ldsm4(uint32_t* r, uint32_t addr) {
    asm volatile("ldmatrix.sync.aligned.m8n8.x4.shared.b16 {%0,%1,%2,%3}, [%4];"
        : "=r"(r[0]), "=r"(r[1]), "=r"(r[2]), "=r"(r[3]) : "r"(addr));
}
// split (a,b) into fp16 hi pair + fp16 residual pair (~22 effective bits)
__device__ __forceinline__ void hsplit(float a, float b, uint32_t& hi, uint32_t& lo) {
    __half ah = __float2half_rn(a);
    __half bh = __float2half_rn(b);
    __half al = __float2half_rn(a - __half2float(ah));
    __half bl = __float2half_rn(b - __half2float(bh));
    hi = ((uint32_t)__half_as_ushort(bh) << 16) | (uint32_t)__half_as_ushort(ah);
    lo = ((uint32_t)__half_as_ushort(bl) << 16) | (uint32_t)__half_as_ushort(al);
}
__device__ __forceinline__ uint32_t hpack(float a, float b) {
    return ((uint32_t)__half_as_ushort(__float2half_rn(b)) << 16)
         | (uint32_t)__half_as_ushort(__float2half_rn(a));
}

// tiny transpose: out[n][h] = in[h][n], 256x256
__global__ void transp256(const float* __restrict__ in, float* __restrict__ out) {
    out[(size_t)threadIdx.x * 256 + blockIdx.x] = in[(size_t)blockIdx.x * 256 + threadIdx.x];
}

// =====================================================================
// fp16 single-term GEMM (tf32-class precision): C = A'.W^T + bias.
// 128x128, 256 thr, warps 2m x 4n, warp tile 64x32. smem 69632B.
// =====================================================================
template<bool GATHER>
__global__ void __launch_bounds__(256) gemm_bf(
    const float* __restrict__ A, const int* __restrict__ tokens,
    const float* __restrict__ W, const float* __restrict__ bias,
    float* __restrict__ C, int Ntot, int K)
{
    extern __shared__ uint32_t smg[];
    uint32_t* Ahi = smg;                  // [128][68]
    uint32_t* Whi = smg + 128 * 68;
    const int tid = threadIdx.x, lane = tid & 31, w = tid >> 5;
    const int g = lane >> 2, tg = lane & 3;
    const int m0 = blockIdx.y * 128, n0 = blockIdx.x * 128;
    const int mwo = (w >> 2) * 64, nwo = (w & 3) * 32;

    const int lr = tid >> 1;
    size_t arow;
    if (GATHER) arow = (size_t)tokens[m0 + lr] * K;
    else        arow = (size_t)(m0 + lr) * K;
    const size_t wrow = (size_t)(n0 + lr) * K;

    float acc[4][4][4];
#pragma unroll
    for (int a = 0; a < 4; a++)
#pragma unroll
        for (int b = 0; b < 4; b++)
#pragma unroll
            for (int c = 0; c < 4; c++) acc[a][b][c] = 0.f;

    for (int kc = 0; kc < K; kc += 128) {
#pragma unroll
        for (int i = 0; i < 16; i++) {
            int col = i * 8 + (tid & 1) * 4;
            float4 av = *(const float4*)(A + arow + kc + col);
            float4 wv = *(const float4*)(W + wrow + kc + col);
            int wd = col >> 1;
            Ahi[lr * 68 + wd]     = hpack(av.x, av.y);
            Ahi[lr * 68 + wd + 1] = hpack(av.z, av.w);
            Whi[lr * 68 + wd]     = hpack(wv.x, wv.y);
            Whi[lr * 68 + wd + 1] = hpack(wv.z, wv.w);
        }
        __syncthreads();
#pragma unroll
        for (int kk = 0; kk < 8; kk++) {
            uint32_t ah[4][4];
#pragma unroll
            for (int mt = 0; mt < 4; mt++) {
                const uint32_t* p = Ahi + (mwo + mt * 16 + g) * 68 + kk * 8 + tg;
                ah[mt][0] = p[0]; ah[mt][1] = p[8 * 68];
                ah[mt][2] = p[4]; ah[mt][3] = p[8 * 68 + 4];
            }
#pragma unroll
            for (int nt = 0; nt < 4; nt++) {
                const uint32_t* qh = Whi + (nwo + nt * 8 + g) * 68 + kk * 8 + tg;
                uint32_t b0 = qh[0], b1 = qh[4];
#pragma unroll
                for (int mt = 0; mt < 4; mt++)
                    mma_f16(acc[mt][nt], ah[mt], b0, b1);
            }
        }
        __syncthreads();
    }
#pragma unroll
    for (int mt = 0; mt < 4; mt++) {
        int r0 = m0 + mwo + mt * 16 + g;
#pragma unroll
        for (int nt = 0; nt < 4; nt++) {
            int col = n0 + nwo + nt * 8 + tg * 2;
            float2 bv = *(const float2*)(bias + col);
            float2 o0 = make_float2(acc[mt][nt][0] + bv.x, acc[mt][nt][1] + bv.y);
            float2 o1 = make_float2(acc[mt][nt][2] + bv.x, acc[mt][nt][3] + bv.y);
            *(float2*)(C + (size_t)r0 * Ntot + col) = o0;
            *(float2*)(C + (size_t)(r0 + 8) * Ntot + col) = o1;
        }
    }
}

// =====================================================================
// fp16 single-term attention: logit[m]=sum_n tanh(A.Wt[n]+bias)*proj.
// BM=128, N=256 full, K-chunks 64. smem 55296B.
// =====================================================================
__global__ void __launch_bounds__(256) att_bf(
    const float* __restrict__ A, const float* __restrict__ Wt,
    const float* __restrict__ bias, const float* __restrict__ proj,
    float* __restrict__ logit)
{
    extern __shared__ uint32_t sma[];
    uint32_t* Ahi = sma;                  // [128][36]
    uint32_t* Whi = sma + 128 * 36;       // [256][36]
    const int tid = threadIdx.x, lane = tid & 31, w = tid >> 5;
    const int g = lane >> 2, tg = lane & 3;
    const int m0 = blockIdx.x * 128;
    const int mwo = (w >> 2) * 64, nwo = (w & 3) * 64;

    const int alr = tid >> 1;

    float acc[4][8][4];
#pragma unroll
    for (int a = 0; a < 4; a++)
#pragma unroll
        for (int b = 0; b < 8; b++)
#pragma unroll
            for (int c = 0; c < 4; c++) acc[a][b][c] = 0.f;

    for (int kc = 0; kc < 256; kc += 64) {
#pragma unroll
        for (int i = 0; i < 8; i++) {
            int col = i * 8 + (tid & 1) * 4;
            float4 av = *(const float4*)(A + (size_t)(m0 + alr) * 256 + kc + col);
            int wd = col >> 1;
            Ahi[alr * 36 + wd]     = hpack(av.x, av.y);
            Ahi[alr * 36 + wd + 1] = hpack(av.z, av.w);
        }
#pragma unroll
        for (int i = 0; i < 16; i++) {
            int col = i * 4;
            float4 wv = *(const float4*)(Wt + (size_t)tid * 256 + kc + col);
            int wd = col >> 1;
            Whi[tid * 36 + wd]     = hpack(wv.x, wv.y);
            Whi[tid * 36 + wd + 1] = hpack(wv.z, wv.w);
        }
        __syncthreads();
#pragma unroll
        for (int kk = 0; kk < 4; kk++) {
            uint32_t ah[4][4];
#pragma unroll
            for (int mt = 0; mt < 4; mt++) {
                const uint32_t* p = Ahi + (mwo + mt * 16 + g) * 36 + kk * 8 + tg;
                ah[mt][0] = p[0]; ah[mt][1] = p[8 * 36];
                ah[mt][2] = p[4]; ah[mt][3] = p[8 * 36 + 4];
            }
#pragma unroll
            for (int nt = 0; nt < 8; nt++) {
                const uint32_t* qh = Whi + (nwo + nt * 8 + g) * 36 + kk * 8 + tg;
                uint32_t b0 = qh[0], b1 = qh[4];
#pragma unroll
                for (int mt = 0; mt < 4; mt++)
                    mma_f16(acc[mt][nt], ah[mt], b0, b1);
            }
        }
        __syncthreads();
    }
    float* red = (float*)sma;
#pragma unroll
    for (int mt = 0; mt < 4; mt++) {
        float pa = 0.f, pb = 0.f;
#pragma unroll
        for (int nt = 0; nt < 8; nt++) {
            int col = nwo + nt * 8 + tg * 2;
            float2 bv = *(const float2*)(bias + col);
            float2 pv = *(const float2*)(proj + col);
            pa += tanh_clamped(acc[mt][nt][0] + bv.x) * pv.x
                + tanh_clamped(acc[mt][nt][1] + bv.y) * pv.y;
            pb += tanh_clamped(acc[mt][nt][2] + bv.x) * pv.x
                + tanh_clamped(acc[mt][nt][3] + bv.y) * pv.y;
        }
        pa += __shfl_xor_sync(0xffffffffu, pa, 1);
        pa += __shfl_xor_sync(0xffffffffu, pa, 2);
        pb += __shfl_xor_sync(0xffffffffu, pb, 1);
        pb += __shfl_xor_sync(0xffffffffu, pb, 2);
        if (tg == 0) {
            red[(mwo + mt * 16 + g) * 4 + (w & 3)] = pa;
            red[(mwo + mt * 16 + g + 8) * 4 + (w & 3)] = pb;
        }
    }
    __syncthreads();
    if (tid < 128) {
        float s = red[tid * 4] + red[tid * 4 + 1] + red[tid * 4 + 2] + red[tid * 4 + 3];
        logit[m0 + tid] = s;
    }
}

// =====================================================================
// TC GRU recurrence, 16 warps, fp16 2-term, templated MT. (unchanged)
// =====================================================================
template<int MT>
__global__ void __launch_bounds__(512) gru_rec_tc(
    const float* __restrict__ xg, float* __restrict__ out,
    const float* __restrict__ Whh, const float* __restrict__ bhh,
    int nsteps, size_t chain_xg, size_t chain_out)
{
    extern __shared__ uint32_t smr[];
    uint32_t* Bsh = smr;                 // 24576 u32 (uint2 per lane-entry)
    uint32_t* hhi = smr + 24576;         // [16*MT][68]
    uint32_t* hlo = hhi + 16 * MT * 68;  // [16*MT][68]

    const int tid = threadIdx.x, lane = tid & 31, wrp = tid >> 5;  // 0..15
    const int g = lane >> 2, tg = lane & 3;
    const int dir = blockIdx.y, chain = blockIdx.z;
    const int bCTA = blockIdx.x * 16 * MT;

    const float* wsrc = Whh + (size_t)dir * 384 * 128;
#pragma unroll 2
    for (int ks = 0; ks < 8; ks++)
#pragma unroll
        for (int tt = 0; tt < 3; tt++) {
            int n = tt * 128 + wrp * 8 + g;
            int k = ks * 16 + tg * 2;
            const float* p = wsrc + (size_t)n * 128 + k;
            uint2* dst = (uint2*)Bsh + ((wrp * 8 + ks) * 3 + tt) * 32 + lane;
            *dst = make_uint2(hpack(p[0], p[1]), hpack(p[8], p[9]));
        }
    for (int idx = tid; idx < 16 * MT * 68; idx += 512) { hhi[idx] = 0u; hlo[idx] = 0u; }

    float bn[3][2];
#pragma unroll
    for (int tt = 0; tt < 3; tt++) {
        int n0 = tt * 128 + wrp * 8 + tg * 2;
        float2 v = *(const float2*)(bhh + dir * 384 + n0);
        bn[tt][0] = v.x; bn[tt][1] = v.y;
    }
    float hreg[MT][4];
#pragma unroll
    for (int a = 0; a < MT; a++)
#pragma unroll
        for (int c = 0; c < 4; c++) hreg[a][c] = 0.f;

    uint32_t hhi_sa = (uint32_t)__cvta_generic_to_shared(hhi);
    uint32_t hlo_sa = (uint32_t)__cvta_generic_to_shared(hlo);
    const uint32_t lmoff = (uint32_t)(((lane & 15) * 68 + (lane >> 4) * 4) * 4);

    const float* xbase = xg + chain * chain_xg + dir * 384;
    float* obase = out + chain * chain_out + dir * 128;
    __syncthreads();

    for (int stp = 0; stp < nsteps; stp++) {
        const int t = dir ? (nsteps - 1 - stp) : stp;
        float2 xvv[MT][3][2];
        const float* xrow = xbase + ((size_t)t * 64 + bCTA) * 768;
#pragma unroll
        for (int mt = 0; mt < MT; mt++)
#pragma unroll
            for (int tt = 0; tt < 3; tt++) {
                int n0 = tt * 128 + wrp * 8 + tg * 2;
                xvv[mt][tt][0] = *(const float2*)(xrow + (size_t)(mt * 16 + g) * 768 + n0);
                xvv[mt][tt][1] = *(const float2*)(xrow + (size_t)(mt * 16 + g + 8) * 768 + n0);
            }

        float acc[MT][3][4], acc2[MT][3][4];
#pragma unroll
        for (int mt = 0; mt < MT; mt++)
#pragma unroll
            for (int tt = 0; tt < 3; tt++) {
                acc[mt][tt][0] = bn[tt][0]; acc[mt][tt][1] = bn[tt][1];
                acc[mt][tt][2] = bn[tt][0]; acc[mt][tt][3] = bn[tt][1];
                acc2[mt][tt][0] = 0.f; acc2[mt][tt][1] = 0.f;
                acc2[mt][tt][2] = 0.f; acc2[mt][tt][3] = 0.f;
            }

#pragma unroll
        for (int ks = 0; ks < 8; ks++) {
            uint32_t ahi[MT][4], alo[MT][4];
#pragma unroll
            for (int mt = 0; mt < MT; mt++) {
                uint32_t off = lmoff + (uint32_t)(mt * 16 * 68 * 4 + ks * 32);
                ldsm4(ahi[mt], hhi_sa + off);
                ldsm4(alo[mt], hlo_sa + off);
            }
#pragma unroll
            for (int tt = 0; tt < 3; tt++) {
                uint2 bb = *((const uint2*)Bsh + ((wrp * 8 + ks) * 3 + tt) * 32 + lane);
#pragma unroll
                for (int mt = 0; mt < MT; mt++) {
                    mma_f16(acc[mt][tt],  ahi[mt], bb.x, bb.y);   // hi*W
                    mma_f16(acc2[mt][tt], alo[mt], bb.x, bb.y);   // lo*W (indep chain)
                }
            }
        }
        float hnew[MT][4];
#pragma unroll
        for (int mt = 0; mt < MT; mt++) {
            const float* xr = (const float*)xvv[mt][0];
            const float* xz = (const float*)xvv[mt][1];
            const float* xn = (const float*)xvv[mt][2];
#pragma unroll
            for (int c = 0; c < 4; c++) {
                float rr = sigf(xr[c] + acc[mt][0][c] + acc2[mt][0][c]);
                float zz = sigf(xz[c] + acc[mt][1][c] + acc2[mt][1][c]);
                float nn = tanh_clamped(xn[c] + rr * (acc[mt][2][c] + acc2[mt][2][c]));
                float h  = (1.f - zz) * nn + zz * hreg[mt][c];
                hreg[mt][c] = h;
                hnew[mt][c] = h;
            }
        }
        __syncthreads();   // all ldmatrix reads of old h done
        const int wcol = wrp * 4 + tg;
#pragma unroll
        for (int mt = 0; mt < MT; mt++) {
            int r0 = mt * 16 + g, r1 = r0 + 8;
            uint32_t hi, lo;
            hsplit(hnew[mt][0], hnew[mt][1], hi, lo);
            hhi[r0 * 68 + wcol] = hi; hlo[r0 * 68 + wcol] = lo;
            hsplit(hnew[mt][2], hnew[mt][3], hi, lo);
            hhi[r1 * 68 + wcol] = hi; hlo[r1 * 68 + wcol] = lo;
            int j0 = wrp * 8 + tg * 2;
            *(float2*)(obase + ((size_t)t * 64 + bCTA + r0) * 256 + j0) =
                make_float2(hnew[mt][0], hnew[mt][1]);
            *(float2*)(obase + ((size_t)t * 64 + bCTA + r1) * 256 + j0) =
                make_float2(hnew[mt][2], hnew[mt][3]);
        }
        __syncthreads();   // new h visible before next step's ldmatrix
    }
}

// ===================== softmax over T + weighted sum =================
__global__ void __launch_bounds__(256) softk(
    const float* __restrict__ logit, const float* __restrict__ out1,
    float* __restrict__ sent)
{
    const int s = blockIdx.x, b = blockIdx.y, tid = threadIdx.x;
    __shared__ float w[64];
    if (tid < 64) w[tid] = logit[(s * 64 + tid) * 64 + b];
    __syncthreads();
    if (tid < 32) {
        float a0 = w[tid], a1 = w[tid + 32];
        float mx = fmaxf(a0, a1);
#pragma unroll
        for (int off = 16; off > 0; off >>= 1)
            mx = fmaxf(mx, __shfl_xor_sync(0xffffffffu, mx, off));
        float e0 = __expf(a0 - mx), e1 = __expf(a1 - mx);
        float sum = e0 + e1;
#pragma unroll
        for (int off = 16; off > 0; off >>= 1)
            sum += __shfl_xor_sync(0xffffffffu, sum, off);
        float inv = 1.f / sum;
        w[tid] = e0 * inv; w[tid + 32] = e1 * inv;
    }
    __syncthreads();
    float acc = 0.f;
    const float* base = out1 + ((size_t)s * 64 * 64 + b) * 256 + tid;
#pragma unroll 8
    for (int t = 0; t < 64; t++)
        acc += w[t] * base[(size_t)t * 64 * 256];
    sent[(size_t)(s * 64 + b) * 256 + tid] = acc;
}

// ===================== final: doc vec + linear =======================
__global__ void __launch_bounds__(256) finalk(
    const float* __restrict__ out2, const float* __restrict__ a2,
    const float* __restrict__ Wf, const float* __restrict__ bf,
    float* __restrict__ out)
{
    const int b = blockIdx.x, tid = threadIdx.x;
    __shared__ float doc[256];
    float acc = 0.f;
#pragma unroll 8
    for (int s = 0; s < 32; s++)
        acc += a2[s * 64 + b] * out2[(size_t)(s * 64 + b) * 256 + tid];
    doc[tid] = acc;
    __syncthreads();
    if (tid < 5) {
        float r = bf[tid];
        for (int h = 0; h < 256; h++) r += doc[h] * Wf[tid * 256 + h];
        out[b * 5 + tid] = r;
    }
}

// =====================================================================
extern "C" void kernel_launch(void* const* d_in, const int* in_sizes, int n_in,
                              void* d_out, int out_size)
{
    (void)in_sizes; (void)n_in; (void)out_size;
    const int*   tokens = (const int*)  d_in[0];
    const float* embed  = (const float*)d_in[1];
    const float* Wih_a  = (const float*)d_in[2];
    const float* Whh_a  = (const float*)d_in[3];
    const float* bih_a  = (const float*)d_in[4];
    const float* bhh_a  = (const float*)d_in[5];
    const float* WW_a   = (const float*)d_in[6];
    const float* b_a    = (const float*)d_in[7];
    const float* proj_a = (const float*)d_in[8];
    const float* Wih_b  = (const float*)d_in[9];
    const float* Whh_b  = (const float*)d_in[10];
    const float* bih_b  = (const float*)d_in[11];
    const float* bhh_b  = (const float*)d_in[12];
    const float* WW_b   = (const float*)d_in[13];
    const float* b_b    = (const float*)d_in[14];
    const float* proj_b = (const float*)d_in[15];
    const float* Wf     = (const float*)d_in[16];
    const float* bf     = (const float*)d_in[17];
    float* out = (float*)d_out;

    float *xg, *out1, *logit, *sent, *xg2, *out2, *a2, *wt;
    cudaGetSymbolAddress((void**)&xg,    g_xg);
    cudaGetSymbolAddress((void**)&out1,  g_out1);
    cudaGetSymbolAddress((void**)&logit, g_logit);
    cudaGetSymbolAddress((void**)&sent,  g_sent);
    cudaGetSymbolAddress((void**)&xg2,   g_xg2);
    cudaGetSymbolAddress((void**)&out2,  g_out2);
    cudaGetSymbolAddress((void**)&a2,    g_a2);
    cudaGetSymbolAddress((void**)&wt,    g_wt);

    const int gru2_smem = (24576 + 2 * 32 * 68) * (int)sizeof(uint32_t);      // 115712
    const int gru1_smem = (24576 + 2 * 16 * 68) * (int)sizeof(uint32_t);      // 107008
    const int gemm_smem = 2 * 128 * 68 * (int)sizeof(uint32_t);               // 69632
    const int att_smem  = (128 * 36 + 256 * 36) * (int)sizeof(uint32_t);      // 55296
    cudaFuncSetAttribute(gru_rec_tc<2>, cudaFuncAttributeMaxDynamicSharedMemorySize, gru2_smem);
    cudaFuncSetAttribute(gru_rec_tc<1>, cudaFuncAttributeMaxDynamicSharedMemorySize, gru1_smem);
    cudaFuncSetAttribute(gemm_bf<true>, cudaFuncAttributeMaxDynamicSharedMemorySize, gemm_smem);
    cudaFuncSetAttribute(gemm_bf<false>,cudaFuncAttributeMaxDynamicSharedMemorySize, gemm_smem);
    cudaFuncSetAttribute(att_bf,        cudaFuncAttributeMaxDynamicSharedMemorySize, att_smem);

    // 0) one-time transposes of the two attention weight matrices
    transp256<<<256, 256>>>(WW_a, wt);
    transp256<<<256, 256>>>(WW_b, wt + 65536);
    // 1) intra input gates: gather(emb) @ Wih_intra^T + bih
    gemm_bf<true><<<dim3(6, 1024), 256, gemm_smem>>>(embed, tokens, Wih_a, bih_a, xg, 768, 128);
    // 2) intra biGRU (MT=2: 32-batch tiles, 128 CTAs)
    gru_rec_tc<2><<<dim3(2, 2, 32), 512, gru2_smem>>>(
        xg, out1, Whh_a, bhh_a, 64, (size_t)64 * 64 * 768, (size_t)64 * 64 * 256);
    // 3) token attention logits
    att_bf<<<1024, 256, att_smem>>>(out1, wt, b_a, proj_a, logit);
    // 4) softmax over tokens + weighted sum
    softk<<<dim3(32, 64), 256>>>(logit, out1, sent);
    // 5) inter input gates
    gemm_bf<false><<<dim3(6, 16), 256, gemm_smem>>>(sent, nullptr, Wih_b, bih_b, xg2, 768, 256);
    // 6) inter biGRU (MT=1: 16-batch tiles, 8 CTAs)
    gru_rec_tc<1><<<dim3(4, 2, 1), 512, gru1_smem>>>(xg2, out2, Whh_b, bhh_b, 32, 0, 0);
    // 7) sentence attention scores (no softmax)
    att_bf<<<16, 256, att_smem>>>(out2, wt + 65536, b_b, proj_b, a2);
    // 8) doc vector + final linear
    finalk<<<64, 256>>>(out2, a2, Wf, bf, out);
}